// round 15
// baseline (speedup 1.0000x reference)
#include <cuda_runtime.h>
#include <math.h>
#include <stdint.h>

// Problem constants
#define Bv 2
#define Tv 2048
#define Cv 1024
#define HSv 8
#define DSv 32
#define HLv 8
#define DLv 128
#define HDv 64
#define WIN_S 256
#define WIN_L 1024

#define NTOT 3584          // packed projection width: 512 qk_s + 512 v_s + 2048 qk_l + 512 v_l
#define NW   4608          // NTOT + 1024 (Wproj)
#define Kdim 1024
#define Mrows (Bv * Tv)    // 4096

// ---------------------------------------------------------------------------
// Scratch (static device globals — allocation-free per harness rules)
// ---------------------------------------------------------------------------
__device__ float g_xt[Mrows * Kdim];     // tf32-rounded x
__device__ float g_Wt[NW * Kdim];        // transposed/packed tf32-rounded weights [n][k]
__device__ float g_c1[Mrows * NTOT];     // packed qkv activations [m][n]
__device__ float g_y [Mrows * Cv];       // attention output (tf32-rounded) [m][1024]

// ---------------------------------------------------------------------------
// Helpers
// ---------------------------------------------------------------------------
__device__ __forceinline__ uint32_t smem_u32(const void* p) {
    uint32_t a;
    asm("{ .reg .u64 t; cvta.to.shared.u64 t, %1; cvt.u32.u64 %0, t; }" : "=r"(a) : "l"(p));
    return a;
}
__device__ __forceinline__ float to_tf32(float x) {
    uint32_t u;
    asm("cvt.rna.tf32.f32 %0, %1;" : "=r"(u) : "f"(x));
    return __uint_as_float(u);
}
__device__ __forceinline__ void cp16(uint32_t dst, const float* src) {
    asm volatile("cp.async.ca.shared.global [%0], [%1], 16;" :: "r"(dst), "l"(src));
}
__device__ __forceinline__ void mma_tf32(float* d, const uint32_t* a, const uint32_t* b) {
    asm volatile(
        "mma.sync.aligned.m16n8k8.row.col.f32.tf32.tf32.f32 "
        "{%0,%1,%2,%3}, {%4,%5,%6,%7}, {%8,%9}, {%0,%1,%2,%3};"
        : "+f"(d[0]), "+f"(d[1]), "+f"(d[2]), "+f"(d[3])
        : "r"(a[0]), "r"(a[1]), "r"(a[2]), "r"(a[3]), "r"(b[0]), "r"(b[1]));
}

// ---------------------------------------------------------------------------
// x -> tf32-rounded copy
// ---------------------------------------------------------------------------
__global__ __launch_bounds__(256) void cvt_x(const float* __restrict__ in,
                                             float* __restrict__ out)
{
    int i = (blockIdx.x * 256 + threadIdx.x) * 4;
    float4 v = *(const float4*)(in + i);
    v.x = to_tf32(v.x); v.y = to_tf32(v.y); v.z = to_tf32(v.z); v.w = to_tf32(v.w);
    *(float4*)(out + i) = v;
}

// ---------------------------------------------------------------------------
// Weight pack + transpose (+ tf32 rounding): Wt[n][k] = tf32(W*[k][n])
// ---------------------------------------------------------------------------
__global__ __launch_bounds__(256) void pack_weights(
    const float* __restrict__ Wqk_s, const float* __restrict__ Wv_s,
    const float* __restrict__ Wqk_l, const float* __restrict__ Wv_l,
    const float* __restrict__ Wproj, float* __restrict__ Wt)
{
    __shared__ float tile[32][33];
    const int n0 = blockIdx.x * 32;
    const int k0 = blockIdx.y * 32;
    const int tx = threadIdx.x & 31, ty = threadIdx.x >> 5;   // 32 x 8

    const int n = n0 + tx;
    const float* src; int w, c;
    if      (n < 512)  { src = Wqk_s; w = 512;  c = n; }
    else if (n < 1024) { src = Wv_s;  w = 512;  c = n - 512; }
    else if (n < 3072) { src = Wqk_l; w = 2048; c = n - 1024; }
    else if (n < 3584) { src = Wv_l;  w = 512;  c = n - 3072; }
    else               { src = Wproj; w = 1024; c = n - 3584; }

    #pragma unroll
    for (int i = 0; i < 4; i++) {
        int k = k0 + ty + i * 8;
        tile[tx][ty + i * 8] = to_tf32(src[(size_t)k * w + c]);
    }
    __syncthreads();
    #pragma unroll
    for (int i = 0; i < 4; i++) {
        int nn = n0 + ty + i * 8;
        Wt[(size_t)nn * Kdim + k0 + tx] = tile[ty + i * 8][tx];
    }
}

// ---------------------------------------------------------------------------
// tf32 mma.sync GEMM: C[m0:+128, n0:+128] = A[m0:+128, :] @ Bt[n0:+128, :]^T
//   A : row-major [*][1024] (tf32-rounded)
//   Bt: row-major [*][1024] (tf32-rounded; rows are N, cols are K)
//   C : row-major, leading dim ldc
// 256 threads = 8 warps (2 x 4), warp tile 64x32, K chunk 32, cp.async
// double buffering.
// ---------------------------------------------------------------------------
#define KC  32
#define LDT 36                       // padded smem row (floats)
#define TFLT (128 * LDT)             // floats per tile buffer
#define NCHUNK (Kdim / KC)           // 32

__global__ __launch_bounds__(256, 2) void mma_gemm(
    const float* __restrict__ A, const float* __restrict__ Bt,
    float* __restrict__ C, int ldc)
{
    extern __shared__ float smf[];
    // layout: As0 [0,TFLT), As1 [TFLT,2T), Bs0 [2T,3T), Bs1 [3T,4T)
    const uint32_t sb = smem_u32(smf);

    const int tid  = threadIdx.x;
    const int warp = tid >> 5, lane = tid & 31;
    const int wm   = warp & 1;          // 0..1 -> 64-row slab
    const int wn   = warp >> 1;         // 0..3 -> 32-col slab
    const int m0   = blockIdx.y * 128;
    const int n0   = blockIdx.x * 128;

    const float* Ag = A  + (size_t)m0 * Kdim;
    const float* Bg = Bt + (size_t)n0 * Kdim;

    // per-thread load slots: 4 rows x one float4 each, per tile
    const int lr = tid >> 3;            // row 0..31 (stepped by 32)
    const int lc = (tid & 7) * 4;       // float offset 0..28

    auto issue = [&](int k0, int bi) {
        const uint32_t baseA = sb + (uint32_t)bi * TFLT * 4;
        const uint32_t baseB = sb + (uint32_t)(2 + bi) * TFLT * 4;
        #pragma unroll
        for (int q = 0; q < 4; q++) {
            int r = lr + q * 32;
            uint32_t off = (uint32_t)(r * LDT + lc) * 4;
            cp16(baseA + off, Ag + (size_t)r * Kdim + k0 + lc);
            cp16(baseB + off, Bg + (size_t)r * Kdim + k0 + lc);
        }
        asm volatile("cp.async.commit_group;");
    };

    float acc[4][4][4] = {};

    issue(0, 0);
    for (int c = 0; c < NCHUNK; c++) {
        const int bi = c & 1;
        if (c + 1 < NCHUNK) {
            issue((c + 1) * KC, bi ^ 1);
            asm volatile("cp.async.wait_group 1;");
        } else {
            asm volatile("cp.async.wait_group 0;");
        }
        __syncthreads();

        const float* Ab = smf + bi * TFLT;
        const float* Bb = smf + (2 + bi) * TFLT;

        #pragma unroll
        for (int k8 = 0; k8 < KC / 8; k8++) {
            const int kb = k8 * 8;
            uint32_t a[4][4], b[4][2];
            #pragma unroll
            for (int mt = 0; mt < 4; mt++) {
                int r  = wm * 64 + mt * 16 + (lane >> 2);
                int cc = kb + (lane & 3);
                a[mt][0] = __float_as_uint(Ab[r * LDT + cc]);
                a[mt][1] = __float_as_uint(Ab[(r + 8) * LDT + cc]);
                a[mt][2] = __float_as_uint(Ab[r * LDT + cc + 4]);
                a[mt][3] = __float_as_uint(Ab[(r + 8) * LDT + cc + 4]);
            }
            #pragma unroll
            for (int nt = 0; nt < 4; nt++) {
                int nrow = wn * 32 + nt * 8 + (lane >> 2);
                int kk   = kb + (lane & 3);
                b[nt][0] = __float_as_uint(Bb[nrow * LDT + kk]);
                b[nt][1] = __float_as_uint(Bb[nrow * LDT + kk + 4]);
            }
            #pragma unroll
            for (int mt = 0; mt < 4; mt++)
                #pragma unroll
                for (int nt = 0; nt < 4; nt++)
                    mma_tf32(acc[mt][nt], a[mt], b[nt]);
        }
        __syncthreads();
    }

    // epilogue: c0 (r, c) c1 (r, c+1) c2 (r+8, c) c3 (r+8, c+1)
    #pragma unroll
    for (int mt = 0; mt < 4; mt++) {
        const int r = m0 + wm * 64 + mt * 16 + (lane >> 2);
        #pragma unroll
        for (int nt = 0; nt < 4; nt++) {
            const int cn = n0 + wn * 32 + nt * 8 + (lane & 3) * 2;
            float2 lo = make_float2(acc[mt][nt][0], acc[mt][nt][1]);
            float2 hi = make_float2(acc[mt][nt][2], acc[mt][nt][3]);
            *(float2*)&C[(size_t)r * ldc + cn]       = lo;
            *(float2*)&C[(size_t)(r + 8) * ldc + cn] = hi;
        }
    }
}

// ---------------------------------------------------------------------------
// Sliding-window flash attention (reads packed activation buffer, stride NTOT)
//   src: [B*T, NTOT]; q at col qOff+h*D, k at kOff+h*D, v at vOff+h*64
//   y  : [B*T, 1024]; writes columns [(headOff+h)*64 .. +63] (tf32-rounded)
// ---------------------------------------------------------------------------
__device__ __forceinline__ float warp_max(float x) {
    #pragma unroll
    for (int o = 16; o; o >>= 1) x = fmaxf(x, __shfl_xor_sync(0xffffffffu, x, o));
    return x;
}
__device__ __forceinline__ float warp_sum(float x) {
    #pragma unroll
    for (int o = 16; o; o >>= 1) x += __shfl_xor_sync(0xffffffffu, x, o);
    return x;
}

template <int D, int W>
__global__ __launch_bounds__(512) void attn_kernel(
    const float* __restrict__ src, int qOff, int kOff, int vOff,
    float* __restrict__ y, int headOff, float scale)
{
    constexpr int BQ = 32, BK = 32, DV = 64;
    constexpr int DP = D + 4;

    __shared__ float Qs[BQ][DP];
    __shared__ float Ks[BK][DP];
    __shared__ float VsT[DV][BK + 4];
    __shared__ float Ps[BQ][BK];

    const int t0   = blockIdx.x * BQ;
    const int h    = blockIdx.y;
    const int b    = blockIdx.z;
    const int tid  = threadIdx.x;
    const int w    = tid >> 5;
    const int lane = tid & 31;

    const float* rowb  = src + (size_t)b * Tv * NTOT;
    const float* qbase = rowb + qOff + h * D;
    const float* kbase = rowb + kOff + h * D;
    const float* vbase = rowb + vOff + h * DV;

    for (int i = tid; i < BQ * (D / 4); i += 512) {
        int r = i / (D / 4), c = (i % (D / 4)) * 4;
        *(float4*)&Qs[r][c] = *(const float4*)(qbase + (size_t)(t0 + r) * NTOT + c);
    }

    const int tA = t0 + w;
    const int tB = t0 + w + 16;
    int lo = t0 - (W - 1); if (lo < 0) lo = 0;
    const int kstart = lo & ~(BK - 1);
    const int kend   = t0 + BQ - 1;

    float mA = -INFINITY, lA = 0.f, a0 = 0.f, a1 = 0.f;
    float mB = -INFINITY, lB = 0.f, b0 = 0.f, b1 = 0.f;

    for (int j0 = kstart; j0 <= kend; j0 += BK) {
        __syncthreads();

        for (int i = tid; i < BK * (D / 4); i += 512) {
            int r = i / (D / 4), c = (i % (D / 4)) * 4;
            *(float4*)&Ks[r][c] = *(const float4*)(kbase + (size_t)(j0 + r) * NTOT + c);
        }
        for (int i = tid; i < BK * (DV / 4); i += 512) {
            int r = i / (DV / 4), c = (i % (DV / 4)) * 4;
            float4 vv = *(const float4*)(vbase + (size_t)(j0 + r) * NTOT + c);
            VsT[c + 0][r] = vv.x;
            VsT[c + 1][r] = vv.y;
            VsT[c + 2][r] = vv.z;
            VsT[c + 3][r] = vv.w;
        }
        __syncthreads();

        const int j = j0 + lane;
        float sA = 0.f, sB = 0.f;
        #pragma unroll
        for (int c = 0; c < D; c += 4) {
            float4 kv = *(const float4*)&Ks[lane][c];
            float4 qa = *(const float4*)&Qs[w][c];
            float4 qb = *(const float4*)&Qs[w + 16][c];
            sA += qa.x * kv.x + qa.y * kv.y + qa.z * kv.z + qa.w * kv.w;
            sB += qb.x * kv.x + qb.y * kv.y + qb.z * kv.z + qb.w * kv.w;
        }
        const bool vA = (j <= tA) && (tA - j < W);
        const bool vB = (j <= tB) && (tB - j < W);
        sA = vA ? sA * scale : -INFINITY;
        sB = vB ? sB * scale : -INFINITY;

        const float tmaxA = warp_max(sA);
        const float tmaxB = warp_max(sB);

        if (tmaxA != -INFINITY) {
            const float mn = fmaxf(mA, tmaxA);
            const float p  = vA ? __expf(sA - mn) : 0.f;
            const float ps = warp_sum(p);
            const float al = __expf(mA - mn);
            lA = lA * al + ps; a0 *= al; a1 *= al; mA = mn;
            Ps[w][lane] = p;
        } else {
            Ps[w][lane] = 0.f;
        }
        if (tmaxB != -INFINITY) {
            const float mn = fmaxf(mB, tmaxB);
            const float p  = vB ? __expf(sB - mn) : 0.f;
            const float ps = warp_sum(p);
            const float al = __expf(mB - mn);
            lB = lB * al + ps; b0 *= al; b1 *= al; mB = mn;
            Ps[w + 16][lane] = p;
        } else {
            Ps[w + 16][lane] = 0.f;
        }
        __syncwarp();

        #pragma unroll
        for (int jj = 0; jj < BK; jj += 4) {
            float4 va = *(const float4*)&VsT[lane][jj];
            float4 vb = *(const float4*)&VsT[lane + 32][jj];
            float4 pa = *(const float4*)&Ps[w][jj];
            float4 pb = *(const float4*)&Ps[w + 16][jj];
            a0 += pa.x * va.x + pa.y * va.y + pa.z * va.z + pa.w * va.w;
            a1 += pa.x * vb.x + pa.y * vb.y + pa.z * vb.z + pa.w * vb.w;
            b0 += pb.x * va.x + pb.y * va.y + pb.z * va.z + pb.w * va.w;
            b1 += pb.x * vb.x + pb.y * vb.y + pb.z * vb.z + pb.w * vb.w;
        }
    }

    const float invA = 1.f / lA;
    const float invB = 1.f / lB;
    float* yA = y + ((size_t)(b * Tv + tA) * Cv) + (headOff + h) * HDv;
    float* yB = y + ((size_t)(b * Tv + tB) * Cv) + (headOff + h) * HDv;
    yA[lane]      = to_tf32(a0 * invA);
    yA[lane + 32] = to_tf32(a1 * invA);
    yB[lane]      = to_tf32(b0 * invB);
    yB[lane + 32] = to_tf32(b1 * invB);
}

// ---------------------------------------------------------------------------
// Launch
// ---------------------------------------------------------------------------
extern "C" void kernel_launch(void* const* d_in, const int* in_sizes, int n_in,
                              void* d_out, int out_size)
{
    const float* x      = (const float*)d_in[0];
    const float* Wqk_s  = (const float*)d_in[1];
    const float* Wv_s   = (const float*)d_in[2];
    const float* Wqk_l  = (const float*)d_in[3];
    const float* Wv_l   = (const float*)d_in[4];
    const float* Wproj  = (const float*)d_in[5];
    float* out = (float*)d_out;

    float *xt, *wt, *c1, *yb;
    cudaGetSymbolAddress((void**)&xt, g_xt);
    cudaGetSymbolAddress((void**)&wt, g_Wt);
    cudaGetSymbolAddress((void**)&c1, g_c1);
    cudaGetSymbolAddress((void**)&yb, g_y);

    const int SMEM = 4 * TFLT * 4;   // 73728 B
    cudaFuncSetAttribute(mma_gemm, cudaFuncAttributeMaxDynamicSharedMemorySize, SMEM);

    // 1) tf32-round x; pack + transpose + round all weights
    cvt_x<<<Mrows * Kdim / (256 * 4), 256>>>(x, xt);
    pack_weights<<<dim3(NW / 32, Kdim / 32), 256>>>(Wqk_s, Wv_s, Wqk_l, Wv_l, Wproj, wt);

    // 2) fused input projections: c1[4096][3584] = xt @ Wt[0:3584]^T
    mma_gemm<<<dim3(NTOT / 128, Mrows / 128), 256, SMEM>>>(xt, wt, c1, NTOT);

    // 3) attention (short heads -> y cols [0,512), long heads -> [512,1024))
    dim3 agrid(Tv / 32, 8, Bv);
    attn_kernel<DSv, WIN_S><<<agrid, 512>>>(c1, 0,    256,  512,  yb, 0,   1.0f / sqrtf((float)DSv));
    attn_kernel<DLv, WIN_L><<<agrid, 512>>>(c1, 1024, 2048, 3072, yb, HSv, 1.0f / sqrtf((float)DLv));

    // 4) output projection: out = y @ Wproj (Wt rows [3584:4608])
    mma_gemm<<<dim3(Cv / 128, Mrows / 128), 256, SMEM>>>(yb, wt + (size_t)NTOT * Kdim, out, Cv);
}

// round 16
// speedup vs baseline: 1.0087x; 1.0087x over previous
#include <cuda_runtime.h>
#include <math.h>
#include <stdint.h>

// Problem constants
#define Bv 2
#define Tv 2048
#define Cv 1024
#define HSv 8
#define DSv 32
#define HLv 8
#define DLv 128
#define HDv 64
#define WIN_S 256
#define WIN_L 1024

#define NTOT 3584          // packed projection width: 512 qk_s + 512 v_s + 2048 qk_l + 512 v_l
#define NW   4608          // NTOT + 1024 (Wproj)
#define Kdim 1024
#define Mrows (Bv * Tv)    // 4096

// ---------------------------------------------------------------------------
// Scratch (static device globals — allocation-free per harness rules)
// ---------------------------------------------------------------------------
__device__ float g_xt[Mrows * Kdim];     // tf32-rounded x
__device__ float g_Wt[NW * Kdim];        // transposed/packed tf32-rounded weights [n][k]
__device__ float g_c1[Mrows * NTOT];     // packed qkv activations [m][n]
__device__ float g_y [Mrows * Cv];       // attention output (tf32-rounded) [m][1024]

// ---------------------------------------------------------------------------
// Helpers
// ---------------------------------------------------------------------------
__device__ __forceinline__ uint32_t smem_u32(const void* p) {
    uint32_t a;
    asm("{ .reg .u64 t; cvta.to.shared.u64 t, %1; cvt.u32.u64 %0, t; }" : "=r"(a) : "l"(p));
    return a;
}
__device__ __forceinline__ float to_tf32(float x) {
    uint32_t u;
    asm("cvt.rna.tf32.f32 %0, %1;" : "=r"(u) : "f"(x));
    return __uint_as_float(u);
}
__device__ __forceinline__ void cp16(uint32_t dst, const float* src) {
    asm volatile("cp.async.ca.shared.global [%0], [%1], 16;" :: "r"(dst), "l"(src));
}
__device__ __forceinline__ void mma_tf32(float* d, const uint32_t* a, const uint32_t* b) {
    asm volatile(
        "mma.sync.aligned.m16n8k8.row.col.f32.tf32.tf32.f32 "
        "{%0,%1,%2,%3}, {%4,%5,%6,%7}, {%8,%9}, {%0,%1,%2,%3};"
        : "+f"(d[0]), "+f"(d[1]), "+f"(d[2]), "+f"(d[3])
        : "r"(a[0]), "r"(a[1]), "r"(a[2]), "r"(a[3]), "r"(b[0]), "r"(b[1]));
}

// ---------------------------------------------------------------------------
// x -> tf32-rounded copy
// ---------------------------------------------------------------------------
__global__ __launch_bounds__(256) void cvt_x(const float* __restrict__ in,
                                             float* __restrict__ out)
{
    int i = (blockIdx.x * 256 + threadIdx.x) * 4;
    float4 v = *(const float4*)(in + i);
    v.x = to_tf32(v.x); v.y = to_tf32(v.y); v.z = to_tf32(v.z); v.w = to_tf32(v.w);
    *(float4*)(out + i) = v;
}

// ---------------------------------------------------------------------------
// Weight pack + transpose (+ tf32 rounding): Wt[n][k] = tf32(W*[k][n])
// ---------------------------------------------------------------------------
__global__ __launch_bounds__(256) void pack_weights(
    const float* __restrict__ Wqk_s, const float* __restrict__ Wv_s,
    const float* __restrict__ Wqk_l, const float* __restrict__ Wv_l,
    const float* __restrict__ Wproj, float* __restrict__ Wt)
{
    __shared__ float tile[32][33];
    const int n0 = blockIdx.x * 32;
    const int k0 = blockIdx.y * 32;
    const int tx = threadIdx.x & 31, ty = threadIdx.x >> 5;   // 32 x 8

    const int n = n0 + tx;
    const float* src; int w, c;
    if      (n < 512)  { src = Wqk_s; w = 512;  c = n; }
    else if (n < 1024) { src = Wv_s;  w = 512;  c = n - 512; }
    else if (n < 3072) { src = Wqk_l; w = 2048; c = n - 1024; }
    else if (n < 3584) { src = Wv_l;  w = 512;  c = n - 3072; }
    else               { src = Wproj; w = 1024; c = n - 3584; }

    #pragma unroll
    for (int i = 0; i < 4; i++) {
        int k = k0 + ty + i * 8;
        tile[tx][ty + i * 8] = to_tf32(src[(size_t)k * w + c]);
    }
    __syncthreads();
    #pragma unroll
    for (int i = 0; i < 4; i++) {
        int nn = n0 + ty + i * 8;
        Wt[(size_t)nn * Kdim + k0 + tx] = tile[ty + i * 8][tx];
    }
}

// ---------------------------------------------------------------------------
// tf32 mma.sync GEMM: C[m0:+128, n0:+128] = A[m0:+128, :] @ Bt[n0:+128, :]^T
//   A : row-major [*][1024] (tf32-rounded)
//   Bt: row-major [*][1024] (tf32-rounded; rows are N, cols are K)
//   C : row-major, leading dim ldc
// 256 threads = 8 warps (2 x 4), warp tile 64x32, K chunk 32, cp.async
// double buffering.
// ---------------------------------------------------------------------------
#define KC  32
#define LDT 36                       // padded smem row (floats)
#define TFLT (128 * LDT)             // floats per tile buffer
#define NCHUNK (Kdim / KC)           // 32

__global__ __launch_bounds__(256, 2) void mma_gemm(
    const float* __restrict__ A, const float* __restrict__ Bt,
    float* __restrict__ C, int ldc)
{
    extern __shared__ float smf[];
    // layout: As0 [0,TFLT), As1 [TFLT,2T), Bs0 [2T,3T), Bs1 [3T,4T)
    const uint32_t sb = smem_u32(smf);

    const int tid  = threadIdx.x;
    const int warp = tid >> 5, lane = tid & 31;
    const int wm   = warp & 1;          // 0..1 -> 64-row slab
    const int wn   = warp >> 1;         // 0..3 -> 32-col slab
    const int m0   = blockIdx.y * 128;
    const int n0   = blockIdx.x * 128;

    const float* Ag = A  + (size_t)m0 * Kdim;
    const float* Bg = Bt + (size_t)n0 * Kdim;

    // per-thread load slots: 4 rows x one float4 each, per tile
    const int lr = tid >> 3;            // row 0..31 (stepped by 32)
    const int lc = (tid & 7) * 4;       // float offset 0..28

    auto issue = [&](int k0, int bi) {
        const uint32_t baseA = sb + (uint32_t)bi * TFLT * 4;
        const uint32_t baseB = sb + (uint32_t)(2 + bi) * TFLT * 4;
        #pragma unroll
        for (int q = 0; q < 4; q++) {
            int r = lr + q * 32;
            uint32_t off = (uint32_t)(r * LDT + lc) * 4;
            cp16(baseA + off, Ag + (size_t)r * Kdim + k0 + lc);
            cp16(baseB + off, Bg + (size_t)r * Kdim + k0 + lc);
        }
        asm volatile("cp.async.commit_group;");
    };

    float acc[4][4][4] = {};

    issue(0, 0);
    for (int c = 0; c < NCHUNK; c++) {
        const int bi = c & 1;
        if (c + 1 < NCHUNK) {
            issue((c + 1) * KC, bi ^ 1);
            asm volatile("cp.async.wait_group 1;");
        } else {
            asm volatile("cp.async.wait_group 0;");
        }
        __syncthreads();

        const float* Ab = smf + bi * TFLT;
        const float* Bb = smf + (2 + bi) * TFLT;

        #pragma unroll
        for (int k8 = 0; k8 < KC / 8; k8++) {
            const int kb = k8 * 8;
            uint32_t a[4][4], b[4][2];
            #pragma unroll
            for (int mt = 0; mt < 4; mt++) {
                int r  = wm * 64 + mt * 16 + (lane >> 2);
                int cc = kb + (lane & 3);
                a[mt][0] = __float_as_uint(Ab[r * LDT + cc]);
                a[mt][1] = __float_as_uint(Ab[(r + 8) * LDT + cc]);
                a[mt][2] = __float_as_uint(Ab[r * LDT + cc + 4]);
                a[mt][3] = __float_as_uint(Ab[(r + 8) * LDT + cc + 4]);
            }
            #pragma unroll
            for (int nt = 0; nt < 4; nt++) {
                int nrow = wn * 32 + nt * 8 + (lane >> 2);
                int kk   = kb + (lane & 3);
                b[nt][0] = __float_as_uint(Bb[nrow * LDT + kk]);
                b[nt][1] = __float_as_uint(Bb[nrow * LDT + kk + 4]);
            }
            #pragma unroll
            for (int mt = 0; mt < 4; mt++)
                #pragma unroll
                for (int nt = 0; nt < 4; nt++)
                    mma_tf32(acc[mt][nt], a[mt], b[nt]);
        }
        __syncthreads();
    }

    // epilogue: c0 (r, c) c1 (r, c+1) c2 (r+8, c) c3 (r+8, c+1)
    #pragma unroll
    for (int mt = 0; mt < 4; mt++) {
        const int r = m0 + wm * 64 + mt * 16 + (lane >> 2);
        #pragma unroll
        for (int nt = 0; nt < 4; nt++) {
            const int cn = n0 + wn * 32 + nt * 8 + (lane & 3) * 2;
            float2 lo = make_float2(acc[mt][nt][0], acc[mt][nt][1]);
            float2 hi = make_float2(acc[mt][nt][2], acc[mt][nt][3]);
            *(float2*)&C[(size_t)r * ldc + cn]       = lo;
            *(float2*)&C[(size_t)(r + 8) * ldc + cn] = hi;
        }
    }
}

// ---------------------------------------------------------------------------
// Sliding-window flash attention (reads packed activation buffer, stride NTOT)
//   src: [B*T, NTOT]; q at col qOff+h*D, k at kOff+h*D, v at vOff+h*64
//   y  : [B*T, 1024]; writes columns [(headOff+h)*64 .. +63] (tf32-rounded)
// ---------------------------------------------------------------------------
__device__ __forceinline__ float warp_max(float x) {
    #pragma unroll
    for (int o = 16; o; o >>= 1) x = fmaxf(x, __shfl_xor_sync(0xffffffffu, x, o));
    return x;
}
__device__ __forceinline__ float warp_sum(float x) {
    #pragma unroll
    for (int o = 16; o; o >>= 1) x += __shfl_xor_sync(0xffffffffu, x, o);
    return x;
}

template <int D, int W>
__global__ __launch_bounds__(512) void attn_kernel(
    const float* __restrict__ src, int qOff, int kOff, int vOff,
    float* __restrict__ y, int headOff, float scale)
{
    constexpr int BQ = 32, BK = 32, DV = 64;
    constexpr int DP = D + 4;

    __shared__ float Qs[BQ][DP];
    __shared__ float Ks[BK][DP];
    __shared__ float VsT[DV][BK + 4];
    __shared__ float Ps[BQ][BK];

    const int t0   = blockIdx.x * BQ;
    const int h    = blockIdx.y;
    const int b    = blockIdx.z;
    const int tid  = threadIdx.x;
    const int w    = tid >> 5;
    const int lane = tid & 31;

    const float* rowb  = src + (size_t)b * Tv * NTOT;
    const float* qbase = rowb + qOff + h * D;
    const float* kbase = rowb + kOff + h * D;
    const float* vbase = rowb + vOff + h * DV;

    for (int i = tid; i < BQ * (D / 4); i += 512) {
        int r = i / (D / 4), c = (i % (D / 4)) * 4;
        *(float4*)&Qs[r][c] = *(const float4*)(qbase + (size_t)(t0 + r) * NTOT + c);
    }

    const int tA = t0 + w;
    const int tB = t0 + w + 16;
    int lo = t0 - (W - 1); if (lo < 0) lo = 0;
    const int kstart = lo & ~(BK - 1);
    const int kend   = t0 + BQ - 1;

    float mA = -INFINITY, lA = 0.f, a0 = 0.f, a1 = 0.f;
    float mB = -INFINITY, lB = 0.f, b0 = 0.f, b1 = 0.f;

    for (int j0 = kstart; j0 <= kend; j0 += BK) {
        __syncthreads();

        for (int i = tid; i < BK * (D / 4); i += 512) {
            int r = i / (D / 4), c = (i % (D / 4)) * 4;
            *(float4*)&Ks[r][c] = *(const float4*)(kbase + (size_t)(j0 + r) * NTOT + c);
        }
        for (int i = tid; i < BK * (DV / 4); i += 512) {
            int r = i / (DV / 4), c = (i % (DV / 4)) * 4;
            float4 vv = *(const float4*)(vbase + (size_t)(j0 + r) * NTOT + c);
            VsT[c + 0][r] = vv.x;
            VsT[c + 1][r] = vv.y;
            VsT[c + 2][r] = vv.z;
            VsT[c + 3][r] = vv.w;
        }
        __syncthreads();

        const int j = j0 + lane;
        float sA = 0.f, sB = 0.f;
        #pragma unroll
        for (int c = 0; c < D; c += 4) {
            float4 kv = *(const float4*)&Ks[lane][c];
            float4 qa = *(const float4*)&Qs[w][c];
            float4 qb = *(const float4*)&Qs[w + 16][c];
            sA += qa.x * kv.x + qa.y * kv.y + qa.z * kv.z + qa.w * kv.w;
            sB += qb.x * kv.x + qb.y * kv.y + qb.z * kv.z + qb.w * kv.w;
        }
        const bool vA = (j <= tA) && (tA - j < W);
        const bool vB = (j <= tB) && (tB - j < W);
        sA = vA ? sA * scale : -INFINITY;
        sB = vB ? sB * scale : -INFINITY;

        const float tmaxA = warp_max(sA);
        const float tmaxB = warp_max(sB);

        if (tmaxA != -INFINITY) {
            const float mn = fmaxf(mA, tmaxA);
            const float p  = vA ? __expf(sA - mn) : 0.f;
            const float ps = warp_sum(p);
            const float al = __expf(mA - mn);
            lA = lA * al + ps; a0 *= al; a1 *= al; mA = mn;
            Ps[w][lane] = p;
        } else {
            Ps[w][lane] = 0.f;
        }
        if (tmaxB != -INFINITY) {
            const float mn = fmaxf(mB, tmaxB);
            const float p  = vB ? __expf(sB - mn) : 0.f;
            const float ps = warp_sum(p);
            const float al = __expf(mB - mn);
            lB = lB * al + ps; b0 *= al; b1 *= al; mB = mn;
            Ps[w + 16][lane] = p;
        } else {
            Ps[w + 16][lane] = 0.f;
        }
        __syncwarp();

        #pragma unroll
        for (int jj = 0; jj < BK; jj += 4) {
            float4 va = *(const float4*)&VsT[lane][jj];
            float4 vb = *(const float4*)&VsT[lane + 32][jj];
            float4 pa = *(const float4*)&Ps[w][jj];
            float4 pb = *(const float4*)&Ps[w + 16][jj];
            a0 += pa.x * va.x + pa.y * va.y + pa.z * va.z + pa.w * va.w;
            a1 += pa.x * vb.x + pa.y * vb.y + pa.z * vb.z + pa.w * vb.w;
            b0 += pb.x * va.x + pb.y * va.y + pb.z * va.z + pb.w * va.w;
            b1 += pb.x * vb.x + pb.y * vb.y + pb.z * vb.z + pb.w * vb.w;
        }
    }

    const float invA = 1.f / lA;
    const float invB = 1.f / lB;
    float* yA = y + ((size_t)(b * Tv + tA) * Cv) + (headOff + h) * HDv;
    float* yB = y + ((size_t)(b * Tv + tB) * Cv) + (headOff + h) * HDv;
    yA[lane]      = to_tf32(a0 * invA);
    yA[lane + 32] = to_tf32(a1 * invA);
    yB[lane]      = to_tf32(b0 * invB);
    yB[lane + 32] = to_tf32(b1 * invB);
}

// ---------------------------------------------------------------------------
// Launch
// ---------------------------------------------------------------------------
extern "C" void kernel_launch(void* const* d_in, const int* in_sizes, int n_in,
                              void* d_out, int out_size)
{
    const float* x      = (const float*)d_in[0];
    const float* Wqk_s  = (const float*)d_in[1];
    const float* Wv_s   = (const float*)d_in[2];
    const float* Wqk_l  = (const float*)d_in[3];
    const float* Wv_l   = (const float*)d_in[4];
    const float* Wproj  = (const float*)d_in[5];
    float* out = (float*)d_out;

    float *xt, *wt, *c1, *yb;
    cudaGetSymbolAddress((void**)&xt, g_xt);
    cudaGetSymbolAddress((void**)&wt, g_Wt);
    cudaGetSymbolAddress((void**)&c1, g_c1);
    cudaGetSymbolAddress((void**)&yb, g_y);

    const int SMEM = 4 * TFLT * 4;   // 73728 B
    cudaFuncSetAttribute(mma_gemm, cudaFuncAttributeMaxDynamicSharedMemorySize, SMEM);

    // 1) tf32-round x; pack + transpose + round all weights
    cvt_x<<<Mrows * Kdim / (256 * 4), 256>>>(x, xt);
    pack_weights<<<dim3(NW / 32, Kdim / 32), 256>>>(Wqk_s, Wv_s, Wqk_l, Wv_l, Wproj, wt);

    // 2) fused input projections: c1[4096][3584] = xt @ Wt[0:3584]^T
    mma_gemm<<<dim3(NTOT / 128, Mrows / 128), 256, SMEM>>>(xt, wt, c1, NTOT);

    // 3) attention (short heads -> y cols [0,512), long heads -> [512,1024))
    dim3 agrid(Tv / 32, 8, Bv);
    attn_kernel<DSv, WIN_S><<<agrid, 512>>>(c1, 0,    256,  512,  yb, 0,   1.0f / sqrtf((float)DSv));
    attn_kernel<DLv, WIN_L><<<agrid, 512>>>(c1, 1024, 2048, 3072, yb, HSv, 1.0f / sqrtf((float)DLv));

    // 4) output projection: out = y @ Wproj (Wt rows [3584:4608])
    mma_gemm<<<dim3(Cv / 128, Mrows / 128), 256, SMEM>>>(yb, wt + (size_t)NTOT * Kdim, out, Cv);
}

// round 17
// speedup vs baseline: 1.0147x; 1.0059x over previous
#include <cuda_runtime.h>
#include <math.h>
#include <stdint.h>

// Problem constants
#define Bv 2
#define Tv 2048
#define Cv 1024
#define HSv 8
#define DSv 32
#define HLv 8
#define DLv 128
#define HDv 64
#define WIN_S 256
#define WIN_L 1024

#define NTOT 3584          // packed projection width: 512 qk_s + 512 v_s + 2048 qk_l + 512 v_l
#define NW   4608          // NTOT + 1024 (Wproj)
#define Kdim 1024
#define Mrows (Bv * Tv)    // 4096

// ---------------------------------------------------------------------------
// Scratch (static device globals — allocation-free per harness rules)
// ---------------------------------------------------------------------------
__device__ float g_xt[Mrows * Kdim];     // tf32-rounded x
__device__ float g_Wt[NW * Kdim];        // transposed/packed tf32-rounded weights [n][k]
__device__ float g_c1[Mrows * NTOT];     // packed qkv activations [m][n]
__device__ float g_y [Mrows * Cv];       // attention output (tf32-rounded) [m][1024]

// ---------------------------------------------------------------------------
// Helpers
// ---------------------------------------------------------------------------
__device__ __forceinline__ uint32_t smem_u32(const void* p) {
    uint32_t a;
    asm("{ .reg .u64 t; cvta.to.shared.u64 t, %1; cvt.u32.u64 %0, t; }" : "=r"(a) : "l"(p));
    return a;
}
__device__ __forceinline__ float to_tf32(float x) {
    uint32_t u;
    asm("cvt.rna.tf32.f32 %0, %1;" : "=r"(u) : "f"(x));
    return __uint_as_float(u);
}
__device__ __forceinline__ void cp16(uint32_t dst, const float* src) {
    asm volatile("cp.async.ca.shared.global [%0], [%1], 16;" :: "r"(dst), "l"(src));
}
__device__ __forceinline__ void mma_tf32(float* d, const uint32_t* a, const uint32_t* b) {
    asm volatile(
        "mma.sync.aligned.m16n8k8.row.col.f32.tf32.tf32.f32 "
        "{%0,%1,%2,%3}, {%4,%5,%6,%7}, {%8,%9}, {%0,%1,%2,%3};"
        : "+f"(d[0]), "+f"(d[1]), "+f"(d[2]), "+f"(d[3])
        : "r"(a[0]), "r"(a[1]), "r"(a[2]), "r"(a[3]), "r"(b[0]), "r"(b[1]));
}

// ---------------------------------------------------------------------------
// x -> tf32-rounded copy
// ---------------------------------------------------------------------------
__global__ __launch_bounds__(256) void cvt_x(const float* __restrict__ in,
                                             float* __restrict__ out)
{
    int i = (blockIdx.x * 256 + threadIdx.x) * 4;
    float4 v = *(const float4*)(in + i);
    v.x = to_tf32(v.x); v.y = to_tf32(v.y); v.z = to_tf32(v.z); v.w = to_tf32(v.w);
    *(float4*)(out + i) = v;
}

// ---------------------------------------------------------------------------
// Weight pack + transpose (+ tf32 rounding): Wt[n][k] = tf32(W*[k][n])
// ---------------------------------------------------------------------------
__global__ __launch_bounds__(256) void pack_weights(
    const float* __restrict__ Wqk_s, const float* __restrict__ Wv_s,
    const float* __restrict__ Wqk_l, const float* __restrict__ Wv_l,
    const float* __restrict__ Wproj, float* __restrict__ Wt)
{
    __shared__ float tile[32][33];
    const int n0 = blockIdx.x * 32;
    const int k0 = blockIdx.y * 32;
    const int tx = threadIdx.x & 31, ty = threadIdx.x >> 5;   // 32 x 8

    const int n = n0 + tx;
    const float* src; int w, c;
    if      (n < 512)  { src = Wqk_s; w = 512;  c = n; }
    else if (n < 1024) { src = Wv_s;  w = 512;  c = n - 512; }
    else if (n < 3072) { src = Wqk_l; w = 2048; c = n - 1024; }
    else if (n < 3584) { src = Wv_l;  w = 512;  c = n - 3072; }
    else               { src = Wproj; w = 1024; c = n - 3584; }

    #pragma unroll
    for (int i = 0; i < 4; i++) {
        int k = k0 + ty + i * 8;
        tile[tx][ty + i * 8] = to_tf32(src[(size_t)k * w + c]);
    }
    __syncthreads();
    #pragma unroll
    for (int i = 0; i < 4; i++) {
        int nn = n0 + ty + i * 8;
        Wt[(size_t)nn * Kdim + k0 + tx] = tile[ty + i * 8][tx];
    }
}

// ---------------------------------------------------------------------------
// tf32 mma.sync GEMM: C[m0:+128, n0:+128] = A[m0:+128, :] @ Bt[n0:+128, :]^T
//   A : row-major [*][1024] (tf32-rounded)
//   Bt: row-major [*][1024] (tf32-rounded; rows are N, cols are K)
//   C : row-major, leading dim ldc
// 256 threads = 8 warps (2 x 4), warp tile 64x32, K chunk 32, cp.async
// double buffering.
// ---------------------------------------------------------------------------
#define KC  32
#define LDT 36                       // padded smem row (floats)
#define TFLT (128 * LDT)             // floats per tile buffer
#define NCHUNK (Kdim / KC)           // 32

__global__ __launch_bounds__(256, 2) void mma_gemm(
    const float* __restrict__ A, const float* __restrict__ Bt,
    float* __restrict__ C, int ldc)
{
    extern __shared__ float smf[];
    // layout: As0 [0,TFLT), As1 [TFLT,2T), Bs0 [2T,3T), Bs1 [3T,4T)
    const uint32_t sb = smem_u32(smf);

    const int tid  = threadIdx.x;
    const int warp = tid >> 5, lane = tid & 31;
    const int wm   = warp & 1;          // 0..1 -> 64-row slab
    const int wn   = warp >> 1;         // 0..3 -> 32-col slab
    const int m0   = blockIdx.y * 128;
    const int n0   = blockIdx.x * 128;

    const float* Ag = A  + (size_t)m0 * Kdim;
    const float* Bg = Bt + (size_t)n0 * Kdim;

    // per-thread load slots: 4 rows x one float4 each, per tile
    const int lr = tid >> 3;            // row 0..31 (stepped by 32)
    const int lc = (tid & 7) * 4;       // float offset 0..28

    auto issue = [&](int k0, int bi) {
        const uint32_t baseA = sb + (uint32_t)bi * TFLT * 4;
        const uint32_t baseB = sb + (uint32_t)(2 + bi) * TFLT * 4;
        #pragma unroll
        for (int q = 0; q < 4; q++) {
            int r = lr + q * 32;
            uint32_t off = (uint32_t)(r * LDT + lc) * 4;
            cp16(baseA + off, Ag + (size_t)r * Kdim + k0 + lc);
            cp16(baseB + off, Bg + (size_t)r * Kdim + k0 + lc);
        }
        asm volatile("cp.async.commit_group;");
    };

    float acc[4][4][4] = {};

    issue(0, 0);
    for (int c = 0; c < NCHUNK; c++) {
        const int bi = c & 1;
        if (c + 1 < NCHUNK) {
            issue((c + 1) * KC, bi ^ 1);
            asm volatile("cp.async.wait_group 1;");
        } else {
            asm volatile("cp.async.wait_group 0;");
        }
        __syncthreads();

        const float* Ab = smf + bi * TFLT;
        const float* Bb = smf + (2 + bi) * TFLT;

        #pragma unroll
        for (int k8 = 0; k8 < KC / 8; k8++) {
            const int kb = k8 * 8;
            uint32_t a[4][4], b[4][2];
            #pragma unroll
            for (int mt = 0; mt < 4; mt++) {
                int r  = wm * 64 + mt * 16 + (lane >> 2);
                int cc = kb + (lane & 3);
                a[mt][0] = __float_as_uint(Ab[r * LDT + cc]);
                a[mt][1] = __float_as_uint(Ab[(r + 8) * LDT + cc]);
                a[mt][2] = __float_as_uint(Ab[r * LDT + cc + 4]);
                a[mt][3] = __float_as_uint(Ab[(r + 8) * LDT + cc + 4]);
            }
            #pragma unroll
            for (int nt = 0; nt < 4; nt++) {
                int nrow = wn * 32 + nt * 8 + (lane >> 2);
                int kk   = kb + (lane & 3);
                b[nt][0] = __float_as_uint(Bb[nrow * LDT + kk]);
                b[nt][1] = __float_as_uint(Bb[nrow * LDT + kk + 4]);
            }
            #pragma unroll
            for (int mt = 0; mt < 4; mt++)
                #pragma unroll
                for (int nt = 0; nt < 4; nt++)
                    mma_tf32(acc[mt][nt], a[mt], b[nt]);
        }
        __syncthreads();
    }

    // epilogue: c0 (r, c) c1 (r, c+1) c2 (r+8, c) c3 (r+8, c+1)
    #pragma unroll
    for (int mt = 0; mt < 4; mt++) {
        const int r = m0 + wm * 64 + mt * 16 + (lane >> 2);
        #pragma unroll
        for (int nt = 0; nt < 4; nt++) {
            const int cn = n0 + wn * 32 + nt * 8 + (lane & 3) * 2;
            float2 lo = make_float2(acc[mt][nt][0], acc[mt][nt][1]);
            float2 hi = make_float2(acc[mt][nt][2], acc[mt][nt][3]);
            *(float2*)&C[(size_t)r * ldc + cn]       = lo;
            *(float2*)&C[(size_t)(r + 8) * ldc + cn] = hi;
        }
    }
}

// ---------------------------------------------------------------------------
// Sliding-window flash attention (reads packed activation buffer, stride NTOT)
//   src: [B*T, NTOT]; q at col qOff+h*D, k at kOff+h*D, v at vOff+h*64
//   y  : [B*T, 1024]; writes columns [(headOff+h)*64 .. +63] (tf32-rounded)
// ---------------------------------------------------------------------------
__device__ __forceinline__ float warp_max(float x) {
    #pragma unroll
    for (int o = 16; o; o >>= 1) x = fmaxf(x, __shfl_xor_sync(0xffffffffu, x, o));
    return x;
}
__device__ __forceinline__ float warp_sum(float x) {
    #pragma unroll
    for (int o = 16; o; o >>= 1) x += __shfl_xor_sync(0xffffffffu, x, o);
    return x;
}

template <int D, int W>
__global__ __launch_bounds__(512) void attn_kernel(
    const float* __restrict__ src, int qOff, int kOff, int vOff,
    float* __restrict__ y, int headOff, float scale)
{
    constexpr int BQ = 32, BK = 32, DV = 64;
    constexpr int DP = D + 4;

    __shared__ float Qs[BQ][DP];
    __shared__ float Ks[BK][DP];
    __shared__ float VsT[DV][BK + 4];
    __shared__ float Ps[BQ][BK];

    const int t0   = blockIdx.x * BQ;
    const int h    = blockIdx.y;
    const int b    = blockIdx.z;
    const int tid  = threadIdx.x;
    const int w    = tid >> 5;
    const int lane = tid & 31;

    const float* rowb  = src + (size_t)b * Tv * NTOT;
    const float* qbase = rowb + qOff + h * D;
    const float* kbase = rowb + kOff + h * D;
    const float* vbase = rowb + vOff + h * DV;

    for (int i = tid; i < BQ * (D / 4); i += 512) {
        int r = i / (D / 4), c = (i % (D / 4)) * 4;
        *(float4*)&Qs[r][c] = *(const float4*)(qbase + (size_t)(t0 + r) * NTOT + c);
    }

    const int tA = t0 + w;
    const int tB = t0 + w + 16;
    int lo = t0 - (W - 1); if (lo < 0) lo = 0;
    const int kstart = lo & ~(BK - 1);
    const int kend   = t0 + BQ - 1;

    float mA = -INFINITY, lA = 0.f, a0 = 0.f, a1 = 0.f;
    float mB = -INFINITY, lB = 0.f, b0 = 0.f, b1 = 0.f;

    for (int j0 = kstart; j0 <= kend; j0 += BK) {
        __syncthreads();

        for (int i = tid; i < BK * (D / 4); i += 512) {
            int r = i / (D / 4), c = (i % (D / 4)) * 4;
            *(float4*)&Ks[r][c] = *(const float4*)(kbase + (size_t)(j0 + r) * NTOT + c);
        }
        for (int i = tid; i < BK * (DV / 4); i += 512) {
            int r = i / (DV / 4), c = (i % (DV / 4)) * 4;
            float4 vv = *(const float4*)(vbase + (size_t)(j0 + r) * NTOT + c);
            VsT[c + 0][r] = vv.x;
            VsT[c + 1][r] = vv.y;
            VsT[c + 2][r] = vv.z;
            VsT[c + 3][r] = vv.w;
        }
        __syncthreads();

        const int j = j0 + lane;
        float sA = 0.f, sB = 0.f;
        #pragma unroll
        for (int c = 0; c < D; c += 4) {
            float4 kv = *(const float4*)&Ks[lane][c];
            float4 qa = *(const float4*)&Qs[w][c];
            float4 qb = *(const float4*)&Qs[w + 16][c];
            sA += qa.x * kv.x + qa.y * kv.y + qa.z * kv.z + qa.w * kv.w;
            sB += qb.x * kv.x + qb.y * kv.y + qb.z * kv.z + qb.w * kv.w;
        }
        const bool vA = (j <= tA) && (tA - j < W);
        const bool vB = (j <= tB) && (tB - j < W);
        sA = vA ? sA * scale : -INFINITY;
        sB = vB ? sB * scale : -INFINITY;

        const float tmaxA = warp_max(sA);
        const float tmaxB = warp_max(sB);

        if (tmaxA != -INFINITY) {
            const float mn = fmaxf(mA, tmaxA);
            const float p  = vA ? __expf(sA - mn) : 0.f;
            const float ps = warp_sum(p);
            const float al = __expf(mA - mn);
            lA = lA * al + ps; a0 *= al; a1 *= al; mA = mn;
            Ps[w][lane] = p;
        } else {
            Ps[w][lane] = 0.f;
        }
        if (tmaxB != -INFINITY) {
            const float mn = fmaxf(mB, tmaxB);
            const float p  = vB ? __expf(sB - mn) : 0.f;
            const float ps = warp_sum(p);
            const float al = __expf(mB - mn);
            lB = lB * al + ps; b0 *= al; b1 *= al; mB = mn;
            Ps[w + 16][lane] = p;
        } else {
            Ps[w + 16][lane] = 0.f;
        }
        __syncwarp();

        #pragma unroll
        for (int jj = 0; jj < BK; jj += 4) {
            float4 va = *(const float4*)&VsT[lane][jj];
            float4 vb = *(const float4*)&VsT[lane + 32][jj];
            float4 pa = *(const float4*)&Ps[w][jj];
            float4 pb = *(const float4*)&Ps[w + 16][jj];
            a0 += pa.x * va.x + pa.y * va.y + pa.z * va.z + pa.w * va.w;
            a1 += pa.x * vb.x + pa.y * vb.y + pa.z * vb.z + pa.w * vb.w;
            b0 += pb.x * va.x + pb.y * va.y + pb.z * va.z + pb.w * va.w;
            b1 += pb.x * vb.x + pb.y * vb.y + pb.z * vb.z + pb.w * vb.w;
        }
    }

    const float invA = 1.f / lA;
    const float invB = 1.f / lB;
    float* yA = y + ((size_t)(b * Tv + tA) * Cv) + (headOff + h) * HDv;
    float* yB = y + ((size_t)(b * Tv + tB) * Cv) + (headOff + h) * HDv;
    yA[lane]      = to_tf32(a0 * invA);
    yA[lane + 32] = to_tf32(a1 * invA);
    yB[lane]      = to_tf32(b0 * invB);
    yB[lane + 32] = to_tf32(b1 * invB);
}

// ---------------------------------------------------------------------------
// Launch
// ---------------------------------------------------------------------------
extern "C" void kernel_launch(void* const* d_in, const int* in_sizes, int n_in,
                              void* d_out, int out_size)
{
    const float* x      = (const float*)d_in[0];
    const float* Wqk_s  = (const float*)d_in[1];
    const float* Wv_s   = (const float*)d_in[2];
    const float* Wqk_l  = (const float*)d_in[3];
    const float* Wv_l   = (const float*)d_in[4];
    const float* Wproj  = (const float*)d_in[5];
    float* out = (float*)d_out;

    float *xt, *wt, *c1, *yb;
    cudaGetSymbolAddress((void**)&xt, g_xt);
    cudaGetSymbolAddress((void**)&wt, g_Wt);
    cudaGetSymbolAddress((void**)&c1, g_c1);
    cudaGetSymbolAddress((void**)&yb, g_y);

    const int SMEM = 4 * TFLT * 4;   // 73728 B
    cudaFuncSetAttribute(mma_gemm, cudaFuncAttributeMaxDynamicSharedMemorySize, SMEM);

    // 1) tf32-round x; pack + transpose + round all weights
    cvt_x<<<Mrows * Kdim / (256 * 4), 256>>>(x, xt);
    pack_weights<<<dim3(NW / 32, Kdim / 32), 256>>>(Wqk_s, Wv_s, Wqk_l, Wv_l, Wproj, wt);

    // 2) fused input projections: c1[4096][3584] = xt @ Wt[0:3584]^T
    mma_gemm<<<dim3(NTOT / 128, Mrows / 128), 256, SMEM>>>(xt, wt, c1, NTOT);

    // 3) attention (short heads -> y cols [0,512), long heads -> [512,1024))
    dim3 agrid(Tv / 32, 8, Bv);
    attn_kernel<DSv, WIN_S><<<agrid, 512>>>(c1, 0,    256,  512,  yb, 0,   1.0f / sqrtf((float)DSv));
    attn_kernel<DLv, WIN_L><<<agrid, 512>>>(c1, 1024, 2048, 3072, yb, HSv, 1.0f / sqrtf((float)DLv));

    // 4) output projection: out = y @ Wproj (Wt rows [3584:4608])
    mma_gemm<<<dim3(Cv / 128, Mrows / 128), 256, SMEM>>>(yb, wt + (size_t)NTOT * Kdim, out, Cv);
}